// round 14
// baseline (speedup 1.0000x reference)
#include <cuda_runtime.h>
#include <cuda_fp16.h>
#include <math.h>
#include <stdint.h>

#define NROWS 32768
#define DDIM  256
#define EPSV  1e-5f
#define KC    32
#define NCHUNK 8
// Warp-private stage: A 2K | B 4K = 6K per warp; 8 warps = 48K per stage; 2 stages.
#define WARP_STAGE   6144
#define STAGE_BYTES  49152
#define SMEM_DYN     (2 * STAGE_BYTES + 1024)

// ---------------- device scratch (no allocations allowed) ----------------
__device__ __half g_X[NROWS * DDIM];
__device__ __half g_Y[NROWS * DDIM];
__device__ __half g_B[4][DDIM * DDIM];     // B[n][k] = s_k * W[k][n], fp16
__device__ float g_bias [4][DDIM];          // b'[n] = b[n] + sum_k t_k W[k][n]
__device__ float g_sum  [3 * DDIM];
__device__ float g_sumsq[3 * DDIM];
__device__ float g_scale[3 * DDIM];
__device__ float g_shift[3 * DDIM];

// ---------------- helpers ----------------
__device__ __forceinline__ uint32_t sm_u32(const void* p) {
    return (uint32_t)__cvta_generic_to_shared(p);
}
__device__ __forceinline__ float gelu_exact(float x) {
    return 0.5f * x * (1.0f + erff(x * 0.70710678118654752440f));
}
__device__ __forceinline__ uint32_t pack2h(__half a, __half b) {
    __half2 t = __halves2half2(a, b);
    return *reinterpret_cast<uint32_t*>(&t);
}
// SW64 swizzle for 64-byte rows (8-row x 64B atom)
__device__ __forceinline__ uint32_t swz64(uint32_t off) {
    return off ^ ((off >> 3) & 0x30);
}

#define CP16(sm, gp) \
    asm volatile("cp.async.cg.shared.global [%0], [%1], 16;" :: "r"(sm), "l"(gp) : "memory")
#define CP_COMMIT() asm volatile("cp.async.commit_group;" ::: "memory")
#define CP_WAITN(n) asm volatile("cp.async.wait_group %0;" :: "n"(n) : "memory")

#define LDSM_X4(r, addr) \
    asm volatile("ldmatrix.sync.aligned.m8n8.x4.shared.b16 {%0,%1,%2,%3}, [%4];" \
        : "=r"((r)[0]), "=r"((r)[1]), "=r"((r)[2]), "=r"((r)[3]) : "r"(addr))

__device__ __forceinline__ void mma16816(float* c, const uint32_t* a, uint32_t b0, uint32_t b1) {
    asm volatile(
        "mma.sync.aligned.m16n8k16.row.col.f32.f16.f16.f32 "
        "{%0,%1,%2,%3}, {%4,%5,%6,%7}, {%8,%9}, {%0,%1,%2,%3};"
        : "+f"(c[0]), "+f"(c[1]), "+f"(c[2]), "+f"(c[3])
        : "r"(a[0]), "r"(a[1]), "r"(a[2]), "r"(a[3]), "r"(b0), "r"(b1));
}

// ---------------- small kernels ----------------
__global__ void zero_stats_kernel() {
    int i = threadIdx.x;
    if (i < 3 * DDIM) { g_sum[i] = 0.f; g_sumsq[i] = 0.f; }
}

__global__ void finalize_stats_kernel(int layer, const float* __restrict__ g,
                                      const float* __restrict__ be) {
    int c = threadIdx.x;
    const float inv = 1.0f / (float)NROWS;
    float mu  = g_sum  [layer * DDIM + c] * inv;
    float var = g_sumsq[layer * DDIM + c] * inv - mu * mu;
    float s = rsqrtf(var + EPSV) * g[c];
    g_scale[layer * DDIM + c] = s;
    g_shift[layer * DDIM + c] = be[c] - mu * s;
}

__global__ void gather_split_kernel(const int* __restrict__ ids,
                                    const float* __restrict__ table) {
    int idx = blockIdx.x * blockDim.x + threadIdx.x;   // float4 index
    int row = idx >> 6;
    int q   = idx & 63;
    int src = ids[row];
    float4 v = reinterpret_cast<const float4*>(table + (size_t)src * DDIM)[q];
    uint2 o;
    o.x = pack2h(__float2half(v.x), __float2half(v.y));
    o.y = pack2h(__float2half(v.z), __float2half(v.w));
    reinterpret_cast<uint2*>(g_X)[idx] = o;
}

__global__ void prep_w_kernel(const float* __restrict__ W, const float* __restrict__ b,
                              int layer, int use_bn) {
    __shared__ float red[DDIM];
    int n = blockIdx.x, k = threadIdx.x;
    float w = W[k * DDIM + n];
    float s = 1.f, t = 0.f;
    if (use_bn) {
        s = g_scale[(layer - 1) * DDIM + k];
        t = g_shift[(layer - 1) * DDIM + k];
    }
    g_B[layer][n * DDIM + k] = __float2half(w * s);
    red[k] = t * w;
    __syncthreads();
    for (int st = 128; st > 0; st >>= 1) {
        if (k < st) red[k] += red[k + st];
        __syncthreads();
    }
    if (k == 0) g_bias[layer][n] = b[n] + red[0];
}

// ---------------- main fused GEMM layer (HMMA fp16, warp-private staging) ----------
// CTA: M=128 x N=128, 8 warps (4M x 2N), warp tile 32x64, 2 CTAs/SM.
// Each warp stages its OWN A rows (32) and B rows (64) — no CTA barrier in mainloop.
// Sync per chunk: cp.async.wait_group + __syncwarp only.
template<int STATS, int FINAL>
__global__ __launch_bounds__(256, 2)
void gemm_kernel(const __half* __restrict__ A,
                 const __half* __restrict__ B,
                 const float* __restrict__ bias,
                 int layer,
                 float* __restrict__ outF,
                 __half* __restrict__ outH)
{
    extern __shared__ char dyn_smem[];
    const int tid  = threadIdx.x;
    const int lane = tid & 31;
    const int wid  = tid >> 5;
    const int m_warp = (wid >> 1) * 32;          // 4 M-groups
    const int n_warp = (wid & 1) * 64;           // 2 N-groups
    const int r0 = blockIdx.x * 128;
    const int c0 = blockIdx.y * 128;

    const uint32_t dyn0 = sm_u32(dyn_smem);
    const uint32_t su   = (dyn0 + 1023) & ~1023u;           // 1KB-aligned base
    const uint32_t wb0  = su + (uint32_t)wid * WARP_STAGE;  // this warp's slot, stage 0
    const uint32_t wb1  = wb0 + STAGE_BYTES;                //                  stage 1

    float acc[2][8][4];
    #pragma unroll
    for (int i = 0; i < 2; i++)
        #pragma unroll
        for (int j = 0; j < 8; j++)
            #pragma unroll
            for (int q = 0; q < 4; q++) acc[i][j][q] = 0.f;

    // --- per-warp cp.async of one K-chunk (KC=32, 64B rows) into stage c%2 ---
    auto issue = [&](int c) {
        const uint32_t sb = (c & 1) ? wb1 : wb0;
        const int kt = c * KC;
        // A: this warp's 32 rows, 4 x 16B per row; lane = row, q = 0..3
        const __half* arow = A + (size_t)(r0 + m_warp + lane) * DDIM + kt;
        #pragma unroll
        for (int q = 0; q < 4; q++) {
            uint32_t sw = swz64((uint32_t)(lane * 64 + q * 16));
            CP16(sb + sw, arow + q * 8);
        }
        // B: this warp's 64 rows, 4 x 16B per row; idx = lane + i*32
        #pragma unroll
        for (int i = 0; i < 8; i++) {
            int idx = lane + i * 32;
            int row = idx >> 2, q = idx & 3;
            uint32_t sw = swz64((uint32_t)(row * 64 + q * 16));
            CP16(sb + 2048 + sw, B + (size_t)(c0 + n_warp + row) * DDIM + kt + q * 8);
        }
        CP_COMMIT();
    };

    // prologue: fill both stages (per-warp groups, per-thread accounting)
    issue(0); issue(1);

    // A-frag lane addressing (row-major A, 16x16 frag = 4 m8n8), local rows 0..31
    const uint32_t a_row = (uint32_t)(lane & 15);
    const uint32_t a_kh  = (uint32_t)(lane >> 4);
    // B-frag lane addressing (paired j/j+1 in one x4), local rows 0..63
    const uint32_t b_row = (uint32_t)(((lane >> 4) & 1) * 8 + (lane & 7));
    const uint32_t b_kh  = (uint32_t)((lane >> 3) & 1);

    #pragma unroll
    for (int c = 0; c < NCHUNK; c++) {
        if (c < NCHUNK - 1) CP_WAITN(1); else CP_WAITN(0);
        __syncwarp();                      // make lane X's async writes visible to lane Y

        const uint32_t sa = (c & 1) ? wb1 : wb0;
        const uint32_t sbB = sa + 2048;

        // fragment register double-buffers
        uint32_t a_f[2][2][4];        // [ks][i][4]
        uint32_t bh[2][4];            // [buf][4]

        #pragma unroll
        for (int i = 0; i < 2; i++) {
            uint32_t off = (i * 16 + a_row) * 64 + a_kh * 16;
            LDSM_X4(a_f[0][i], sa + swz64(off));
        }
        {
            uint32_t off = b_row * 64 + b_kh * 16;
            LDSM_X4(bh[0], sbB + swz64(off));
        }

        #pragma unroll
        for (int g = 0; g < 8; g++) {      // g = ks*4 + jp
            const int ks = g >> 2, jp = g & 3;
            const int cb = g & 1, nb = cb ^ 1;
            if (g < 7) {
                const int gn = g + 1, ksn = gn >> 2, jpn = gn & 3;
                uint32_t offb = (jpn * 16 + b_row) * 64 + ksn * 32 + b_kh * 16;
                LDSM_X4(bh[nb], sbB + swz64(offb));
                if (jpn == 0) {
                    #pragma unroll
                    for (int i = 0; i < 2; i++) {
                        uint32_t offa = (i * 16 + a_row) * 64 + ksn * 32 + a_kh * 16;
                        LDSM_X4(a_f[ksn][i], sa + swz64(offa));
                    }
                }
            }
            mma16816(acc[0][2 * jp],     a_f[ks][0], bh[cb][0], bh[cb][1]);
            mma16816(acc[1][2 * jp],     a_f[ks][1], bh[cb][0], bh[cb][1]);
            mma16816(acc[0][2 * jp + 1], a_f[ks][0], bh[cb][2], bh[cb][3]);
            mma16816(acc[1][2 * jp + 1], a_f[ks][1], bh[cb][2], bh[cb][3]);
        }

        if (c + 2 < NCHUNK) issue(c + 2);  // refill the stage just consumed
    }

    // ---- epilogue: bias + exact GELU + stores + column stats ----
    #pragma unroll
    for (int j = 0; j < 8; j++) {
        const int col0 = c0 + n_warp + j * 8 + (lane & 3) * 2;
        const float bi0 = bias[col0], bi1 = bias[col0 + 1];
        float su0 = 0.f, su1 = 0.f, sq0 = 0.f, sq1 = 0.f;
        #pragma unroll
        for (int i = 0; i < 2; i++) {
            const int rowA = r0 + m_warp + i * 16 + (lane >> 2);
            float v0 = gelu_exact(acc[i][j][0] + bi0);
            float v1 = gelu_exact(acc[i][j][1] + bi1);
            float v2 = gelu_exact(acc[i][j][2] + bi0);
            float v3 = gelu_exact(acc[i][j][3] + bi1);
            if (STATS) {
                su0 += v0 + v2; su1 += v1 + v3;
                sq0 += v0 * v0 + v2 * v2; sq1 += v1 * v1 + v3 * v3;
            }
            if (FINAL) {
                *reinterpret_cast<float2*>(outF + (size_t)rowA * DDIM + col0)
                    = make_float2(v0, v1);
                *reinterpret_cast<float2*>(outF + (size_t)(rowA + 8) * DDIM + col0)
                    = make_float2(v2, v3);
            } else {
                *reinterpret_cast<uint32_t*>(outH + (size_t)rowA * DDIM + col0)
                    = pack2h(__float2half(v0), __float2half(v1));
                *reinterpret_cast<uint32_t*>(outH + (size_t)(rowA + 8) * DDIM + col0)
                    = pack2h(__float2half(v2), __float2half(v3));
            }
        }
        if (STATS) {
            #pragma unroll
            for (int m = 4; m <= 16; m <<= 1) {
                su0 += __shfl_xor_sync(0xFFFFFFFFu, su0, m);
                su1 += __shfl_xor_sync(0xFFFFFFFFu, su1, m);
                sq0 += __shfl_xor_sync(0xFFFFFFFFu, sq0, m);
                sq1 += __shfl_xor_sync(0xFFFFFFFFu, sq1, m);
            }
            if ((lane >> 2) == 0) {
                atomicAdd(&g_sum  [layer * DDIM + col0],     su0);
                atomicAdd(&g_sum  [layer * DDIM + col0 + 1], su1);
                atomicAdd(&g_sumsq[layer * DDIM + col0],     sq0);
                atomicAdd(&g_sumsq[layer * DDIM + col0 + 1], sq1);
            }
        }
    }
}

// ---------------- launch ----------------
extern "C" void kernel_launch(void* const* d_in, const int* in_sizes, int n_in,
                              void* d_out, int out_size) {
    const int*   ids   = (const int*)  d_in[0];
    const float* table = (const float*)d_in[1];
    const float* W[4]  = {(const float*)d_in[2], (const float*)d_in[4],
                          (const float*)d_in[6], (const float*)d_in[8]};
    const float* b[4]  = {(const float*)d_in[3], (const float*)d_in[5],
                          (const float*)d_in[7], (const float*)d_in[9]};
    const float* g[3]  = {(const float*)d_in[10], (const float*)d_in[12], (const float*)d_in[14]};
    const float* be[3] = {(const float*)d_in[11], (const float*)d_in[13], (const float*)d_in[15]};
    float* out = (float*)d_out;

    cudaFuncSetAttribute(gemm_kernel<1, 0>, cudaFuncAttributeMaxDynamicSharedMemorySize, SMEM_DYN);
    cudaFuncSetAttribute(gemm_kernel<0, 1>, cudaFuncAttributeMaxDynamicSharedMemorySize, SMEM_DYN);

    __half *X, *Y, *Bm;
    float *bs;
    cudaGetSymbolAddress((void**)&X,  g_X);
    cudaGetSymbolAddress((void**)&Y,  g_Y);
    cudaGetSymbolAddress((void**)&Bm, g_B);
    cudaGetSymbolAddress((void**)&bs, g_bias);

    const dim3 grid(NROWS / 128, DDIM / 128), blk(256);

    zero_stats_kernel<<<1, 768>>>();
    gather_split_kernel<<<NROWS * DDIM / 4 / 256, 256>>>(ids, table);
    prep_w_kernel<<<DDIM, DDIM>>>(W[0], b[0], 0, 0);

    gemm_kernel<1, 0><<<grid, blk, SMEM_DYN>>>(
        X, Bm + 0 * DDIM * DDIM, bs + 0 * DDIM, 0, nullptr, Y);
    finalize_stats_kernel<<<1, DDIM>>>(0, g[0], be[0]);
    prep_w_kernel<<<DDIM, DDIM>>>(W[1], b[1], 1, 1);

    gemm_kernel<1, 0><<<grid, blk, SMEM_DYN>>>(
        Y, Bm + 1 * DDIM * DDIM, bs + 1 * DDIM, 1, nullptr, X);
    finalize_stats_kernel<<<1, DDIM>>>(1, g[1], be[1]);
    prep_w_kernel<<<DDIM, DDIM>>>(W[2], b[2], 2, 1);

    gemm_kernel<1, 0><<<grid, blk, SMEM_DYN>>>(
        X, Bm + 2 * DDIM * DDIM, bs + 2 * DDIM, 2, nullptr, Y);
    finalize_stats_kernel<<<1, DDIM>>>(2, g[2], be[2]);
    prep_w_kernel<<<DDIM, DDIM>>>(W[3], b[3], 3, 1);

    gemm_kernel<0, 1><<<grid, blk, SMEM_DYN>>>(
        Y, Bm + 3 * DDIM * DDIM, bs + 3 * DDIM, 3, out, nullptr);
}

// round 15
// speedup vs baseline: 1.2884x; 1.2884x over previous
#include <cuda_runtime.h>
#include <cuda_fp16.h>
#include <math.h>
#include <stdint.h>

#define NROWS 32768
#define DDIM  256
#define EPSV  1e-5f
#define KC    32
#define NCHUNK 8
// SMEM: B 64K (8 chunk-blocks x 8K) | A 4 stages x 8K = 96K (+align slack)
#define B_BYTES      65536
#define A_STAGE      8192
#define SMEM_DYN     (B_BYTES + 4 * A_STAGE + 1024)

// ---------------- device scratch (no allocations allowed) ----------------
__device__ __half g_X[NROWS * DDIM];
__device__ __half g_Y[NROWS * DDIM];
__device__ __half g_B[4][DDIM * DDIM];     // B[n][k] = s_k * W[k][n], fp16
__device__ float g_bias [4][DDIM];          // b'[n] = b[n] + sum_k t_k W[k][n]
__device__ float g_sum  [3 * DDIM];
__device__ float g_sumsq[3 * DDIM];
__device__ float g_scale[3 * DDIM];
__device__ float g_shift[3 * DDIM];

// ---------------- helpers ----------------
__device__ __forceinline__ uint32_t sm_u32(const void* p) {
    return (uint32_t)__cvta_generic_to_shared(p);
}
// Exact-GELU via Abramowitz-Stegun 7.1.26 erf (max abs err ~1.5e-7).
__device__ __forceinline__ float gelu_fast(float x) {
    float z = fabsf(x) * 0.70710678118654752440f;
    float t = __fdividef(1.0f, fmaf(0.3275911f, z, 1.0f));
    float p = fmaf(1.061405429f, t, -1.453152027f);
    p = fmaf(p, t, 1.421413741f);
    p = fmaf(p, t, -0.284496736f);
    p = fmaf(p, t, 0.254829592f);
    p = p * t;
    float e = __expf(-z * z);
    float erf_abs = fmaf(-p, e, 1.0f);          // 1 - p*exp(-z^2), in [0,1]
    float erfv = copysignf(erf_abs, x);
    return 0.5f * x * (1.0f + erfv);
}
__device__ __forceinline__ uint32_t pack2h(__half a, __half b) {
    __half2 t = __halves2half2(a, b);
    return *reinterpret_cast<uint32_t*>(&t);
}
// SW64 swizzle for 64-byte rows (8-row x 64B atom)
__device__ __forceinline__ uint32_t swz64(uint32_t off) {
    return off ^ ((off >> 3) & 0x30);
}

#define CP16(sm, gp) \
    asm volatile("cp.async.cg.shared.global [%0], [%1], 16;" :: "r"(sm), "l"(gp) : "memory")
#define CP_COMMIT() asm volatile("cp.async.commit_group;" ::: "memory")
#define CP_WAITN(n) asm volatile("cp.async.wait_group %0;" :: "n"(n) : "memory")

#define LDSM_X4(r, addr) \
    asm volatile("ldmatrix.sync.aligned.m8n8.x4.shared.b16 {%0,%1,%2,%3}, [%4];" \
        : "=r"((r)[0]), "=r"((r)[1]), "=r"((r)[2]), "=r"((r)[3]) : "r"(addr))

__device__ __forceinline__ void mma16816(float* c, const uint32_t* a, uint32_t b0, uint32_t b1) {
    asm volatile(
        "mma.sync.aligned.m16n8k16.row.col.f32.f16.f16.f32 "
        "{%0,%1,%2,%3}, {%4,%5,%6,%7}, {%8,%9}, {%0,%1,%2,%3};"
        : "+f"(c[0]), "+f"(c[1]), "+f"(c[2]), "+f"(c[3])
        : "r"(a[0]), "r"(a[1]), "r"(a[2]), "r"(a[3]), "r"(b0), "r"(b1));
}

// ---------------- small kernels ----------------
__global__ void zero_stats_kernel() {
    int i = threadIdx.x;
    if (i < 3 * DDIM) { g_sum[i] = 0.f; g_sumsq[i] = 0.f; }
}

__global__ void finalize_stats_kernel(int layer, const float* __restrict__ g,
                                      const float* __restrict__ be) {
    int c = threadIdx.x;
    const float inv = 1.0f / (float)NROWS;
    float mu  = g_sum  [layer * DDIM + c] * inv;
    float var = g_sumsq[layer * DDIM + c] * inv - mu * mu;
    float s = rsqrtf(var + EPSV) * g[c];
    g_scale[layer * DDIM + c] = s;
    g_shift[layer * DDIM + c] = be[c] - mu * s;
}

__global__ void gather_split_kernel(const int* __restrict__ ids,
                                    const float* __restrict__ table) {
    int idx = blockIdx.x * blockDim.x + threadIdx.x;   // float4 index
    int row = idx >> 6;
    int q   = idx & 63;
    int src = ids[row];
    float4 v = reinterpret_cast<const float4*>(table + (size_t)src * DDIM)[q];
    uint2 o;
    o.x = pack2h(__float2half(v.x), __float2half(v.y));
    o.y = pack2h(__float2half(v.z), __float2half(v.w));
    reinterpret_cast<uint2*>(g_X)[idx] = o;
}

__global__ void prep_w_kernel(const float* __restrict__ W, const float* __restrict__ b,
                              int layer, int use_bn) {
    __shared__ float red[DDIM];
    int n = blockIdx.x, k = threadIdx.x;
    float w = W[k * DDIM + n];
    float s = 1.f, t = 0.f;
    if (use_bn) {
        s = g_scale[(layer - 1) * DDIM + k];
        t = g_shift[(layer - 1) * DDIM + k];
    }
    g_B[layer][n * DDIM + k] = __float2half(w * s);
    red[k] = t * w;
    __syncthreads();
    for (int st = 128; st > 0; st >>= 1) {
        if (k < st) red[k] += red[k + st];
        __syncthreads();
    }
    if (k == 0) g_bias[layer][n] = b[n] + red[0];
}

// ---------------- main fused GEMM layer (HMMA fp16, B resident in SMEM) ----------
// CTA: M=128 x N=128, 8 warps (4M x 2N), warp tile 32x64, 2 CTAs/SM.
// B (128 x 256 fp16 = 64KB) loaded ONCE per CTA as cp.async group 0.
// A: K chunks of 32, 4-stage cp.async pipeline, one barrier per chunk.
// Register double-buffered fragments.
template<int STATS, int FINAL>
__global__ __launch_bounds__(256, 2)
void gemm_kernel(const __half* __restrict__ A,
                 const __half* __restrict__ B,
                 const float* __restrict__ bias,
                 int layer,
                 float* __restrict__ outF,
                 __half* __restrict__ outH)
{
    extern __shared__ char dyn_smem[];
    const int tid  = threadIdx.x;
    const int lane = tid & 31;
    const int wid  = tid >> 5;
    const int m_warp = (wid >> 1) * 32;          // 4 M-groups
    const int n_warp = (wid & 1) * 64;           // 2 N-groups
    const int r0 = blockIdx.x * 128;
    const int c0 = blockIdx.y * 128;

    const uint32_t dyn0 = sm_u32(dyn_smem);
    const uint32_t su   = (dyn0 + 1023) & ~1023u;   // 1KB-aligned: B base
    const uint32_t suA  = su + B_BYTES;             // A stages base

    float acc[2][8][4];
    #pragma unroll
    for (int i = 0; i < 2; i++)
        #pragma unroll
        for (int j = 0; j < 8; j++)
            #pragma unroll
            for (int q = 0; q < 4; q++) acc[i][j][q] = 0.f;

    // --- B prologue: 8 chunk-blocks x (128 rows x 64B), 4096 CP16, 16/thread ---
    #pragma unroll
    for (int i = 0; i < 16; i++) {
        int idx = tid + i * 256;          // 0..4095
        int ch  = idx >> 9;               // K-chunk 0..7
        int rem = idx & 511;
        int row = rem >> 2, q = rem & 3;
        uint32_t sw = swz64((uint32_t)(row * 64 + q * 16));
        CP16(su + ch * A_STAGE + sw,
             B + (size_t)(c0 + row) * DDIM + ch * KC + q * 8);
    }
    CP_COMMIT();

    // --- A per-chunk issue (KC=32, 64B rows) into stage c%4 ---
    auto issue = [&](int c) {
        const uint32_t sb = suA + (c & 3) * A_STAGE;
        const int kt = c * KC;
        #pragma unroll
        for (int i = 0; i < 2; i++) {     // 128 rows x 4 x 16B = 512 chunks
            int idx = tid + i * 256;
            int row = idx >> 2, q = idx & 3;
            uint32_t sw = swz64((uint32_t)(row * 64 + q * 16));
            CP16(sb + sw, A + (size_t)(r0 + row) * DDIM + kt + q * 8);
        }
        CP_COMMIT();
    };

    // prologue: fill 3 A stages (groups: B, A0, A1, A2)
    issue(0); issue(1); issue(2);

    // A-frag lane addressing (row-major A, 16x16 frag = 4 m8n8)
    const uint32_t a_row = (uint32_t)(lane & 15);
    const uint32_t a_kh  = (uint32_t)(lane >> 4);
    // B-frag lane addressing (paired j/j+1 in one x4)
    const uint32_t b_row = (uint32_t)(((lane >> 4) & 1) * 8 + (lane & 7));
    const uint32_t b_kh  = (uint32_t)((lane >> 3) & 1);

    #pragma unroll
    for (int c = 0; c < NCHUNK; c++) {
        // pending-group math: entering chunk c, need B + A0..Ac complete.
        if      (c <  NCHUNK - 2) CP_WAITN(2);
        else if (c == NCHUNK - 2) CP_WAITN(1);
        else                      CP_WAITN(0);
        __syncthreads();
        if (c + 3 < NCHUNK) issue(c + 3);

        const uint32_t sa  = suA + (c & 3) * A_STAGE;
        const uint32_t sbB = su + c * A_STAGE;      // resident B chunk block

        uint32_t a_f[2][2][4];        // [ks][i][4]
        uint32_t bh[2][4];            // [buf][4]

        #pragma unroll
        for (int i = 0; i < 2; i++) {
            uint32_t off = (m_warp + i * 16 + a_row) * 64 + a_kh * 16;
            LDSM_X4(a_f[0][i], sa + swz64(off));
        }
        {
            uint32_t off = (n_warp + b_row) * 64 + b_kh * 16;
            LDSM_X4(bh[0], sbB + swz64(off));
        }

        #pragma unroll
        for (int g = 0; g < 8; g++) {      // g = ks*4 + jp
            const int ks = g >> 2, jp = g & 3;
            const int cb = g & 1, nb = cb ^ 1;
            if (g < 7) {
                const int gn = g + 1, ksn = gn >> 2, jpn = gn & 3;
                uint32_t offb = (n_warp + jpn * 16 + b_row) * 64 + ksn * 32 + b_kh * 16;
                LDSM_X4(bh[nb], sbB + swz64(offb));
                if (jpn == 0) {
                    #pragma unroll
                    for (int i = 0; i < 2; i++) {
                        uint32_t offa = (m_warp + i * 16 + a_row) * 64 + ksn * 32 + a_kh * 16;
                        LDSM_X4(a_f[ksn][i], sa + swz64(offa));
                    }
                }
            }
            mma16816(acc[0][2 * jp],     a_f[ks][0], bh[cb][0], bh[cb][1]);
            mma16816(acc[1][2 * jp],     a_f[ks][1], bh[cb][0], bh[cb][1]);
            mma16816(acc[0][2 * jp + 1], a_f[ks][0], bh[cb][2], bh[cb][3]);
            mma16816(acc[1][2 * jp + 1], a_f[ks][1], bh[cb][2], bh[cb][3]);
        }
    }

    // ---- epilogue: bias + fast exact GELU + stores + column stats ----
    #pragma unroll
    for (int j = 0; j < 8; j++) {
        const int col0 = c0 + n_warp + j * 8 + (lane & 3) * 2;
        const float bi0 = bias[col0], bi1 = bias[col0 + 1];
        float su0 = 0.f, su1 = 0.f, sq0 = 0.f, sq1 = 0.f;
        #pragma unroll
        for (int i = 0; i < 2; i++) {
            const int rowA = r0 + m_warp + i * 16 + (lane >> 2);
            float v0 = gelu_fast(acc[i][j][0] + bi0);
            float v1 = gelu_fast(acc[i][j][1] + bi1);
            float v2 = gelu_fast(acc[i][j][2] + bi0);
            float v3 = gelu_fast(acc[i][j][3] + bi1);
            if (STATS) {
                su0 += v0 + v2; su1 += v1 + v3;
                sq0 += v0 * v0 + v2 * v2; sq1 += v1 * v1 + v3 * v3;
            }
            if (FINAL) {
                *reinterpret_cast<float2*>(outF + (size_t)rowA * DDIM + col0)
                    = make_float2(v0, v1);
                *reinterpret_cast<float2*>(outF + (size_t)(rowA + 8) * DDIM + col0)
                    = make_float2(v2, v3);
            } else {
                *reinterpret_cast<uint32_t*>(outH + (size_t)rowA * DDIM + col0)
                    = pack2h(__float2half(v0), __float2half(v1));
                *reinterpret_cast<uint32_t*>(outH + (size_t)(rowA + 8) * DDIM + col0)
                    = pack2h(__float2half(v2), __float2half(v3));
            }
        }
        if (STATS) {
            #pragma unroll
            for (int m = 4; m <= 16; m <<= 1) {
                su0 += __shfl_xor_sync(0xFFFFFFFFu, su0, m);
                su1 += __shfl_xor_sync(0xFFFFFFFFu, su1, m);
                sq0 += __shfl_xor_sync(0xFFFFFFFFu, sq0, m);
                sq1 += __shfl_xor_sync(0xFFFFFFFFu, sq1, m);
            }
            if ((lane >> 2) == 0) {
                atomicAdd(&g_sum  [layer * DDIM + col0],     su0);
                atomicAdd(&g_sum  [layer * DDIM + col0 + 1], su1);
                atomicAdd(&g_sumsq[layer * DDIM + col0],     sq0);
                atomicAdd(&g_sumsq[layer * DDIM + col0 + 1], sq1);
            }
        }
    }
}

// ---------------- launch ----------------
extern "C" void kernel_launch(void* const* d_in, const int* in_sizes, int n_in,
                              void* d_out, int out_size) {
    const int*   ids   = (const int*)  d_in[0];
    const float* table = (const float*)d_in[1];
    const float* W[4]  = {(const float*)d_in[2], (const float*)d_in[4],
                          (const float*)d_in[6], (const float*)d_in[8]};
    const float* b[4]  = {(const float*)d_in[3], (const float*)d_in[5],
                          (const float*)d_in[7], (const float*)d_in[9]};
    const float* g[3]  = {(const float*)d_in[10], (const float*)d_in[12], (const float*)d_in[14]};
    const float* be[3] = {(const float*)d_in[11], (const float*)d_in[13], (const float*)d_in[15]};
    float* out = (float*)d_out;

    cudaFuncSetAttribute(gemm_kernel<1, 0>, cudaFuncAttributeMaxDynamicSharedMemorySize, SMEM_DYN);
    cudaFuncSetAttribute(gemm_kernel<0, 1>, cudaFuncAttributeMaxDynamicSharedMemorySize, SMEM_DYN);

    __half *X, *Y, *Bm;
    float *bs;
    cudaGetSymbolAddress((void**)&X,  g_X);
    cudaGetSymbolAddress((void**)&Y,  g_Y);
    cudaGetSymbolAddress((void**)&Bm, g_B);
    cudaGetSymbolAddress((void**)&bs, g_bias);

    const dim3 grid(NROWS / 128, DDIM / 128), blk(256);

    zero_stats_kernel<<<1, 768>>>();
    gather_split_kernel<<<NROWS * DDIM / 4 / 256, 256>>>(ids, table);
    prep_w_kernel<<<DDIM, DDIM>>>(W[0], b[0], 0, 0);

    gemm_kernel<1, 0><<<grid, blk, SMEM_DYN>>>(
        X, Bm + 0 * DDIM * DDIM, bs + 0 * DDIM, 0, nullptr, Y);
    finalize_stats_kernel<<<1, DDIM>>>(0, g[0], be[0]);
    prep_w_kernel<<<DDIM, DDIM>>>(W[1], b[1], 1, 1);

    gemm_kernel<1, 0><<<grid, blk, SMEM_DYN>>>(
        Y, Bm + 1 * DDIM * DDIM, bs + 1 * DDIM, 1, nullptr, X);
    finalize_stats_kernel<<<1, DDIM>>>(1, g[1], be[1]);
    prep_w_kernel<<<DDIM, DDIM>>>(W[2], b[2], 2, 1);

    gemm_kernel<1, 0><<<grid, blk, SMEM_DYN>>>(
        X, Bm + 2 * DDIM * DDIM, bs + 2 * DDIM, 2, nullptr, Y);
    finalize_stats_kernel<<<1, DDIM>>>(2, g[2], be[2]);
    prep_w_kernel<<<DDIM, DDIM>>>(W[3], b[3], 3, 1);

    gemm_kernel<0, 1><<<grid, blk, SMEM_DYN>>>(
        Y, Bm + 3 * DDIM * DDIM, bs + 3 * DDIM, 3, out, nullptr);
}